// round 15
// baseline (speedup 1.0000x reference)
#include <cuda_runtime.h>
#include <cuda_bf16.h>
#include <cuda_fp16.h>
#include <math.h>
#include <stdint.h>

#define DIM 128
#define NMAX 100000
#define EMAX 2000000

// Scratch (allocation-free rule: __device__ globals)
__device__ __half   g_bufA[(size_t)NMAX * DIM];   // layer-1 messages (fp16, prescaled)
__device__ __half   g_bufB[(size_t)NMAX * DIM];   // final z (fp16)
__device__ __half   g_bufC[(size_t)NMAX * DIM];   // layer-2 messages (fp16, prescaled)
__device__ int      g_deg[NMAX];
__device__ float    g_dinv[NMAX];
__device__ int      g_rowptr[NMAX + 1];
__device__ int      g_cursor[NMAX];
__device__ int      g_csrc[EMAX];
__device__ int      g_bsum[512];
__device__ uint32_t g_Wimg[2][8192];              // [layer][swizzled fp16x2 image 128x128]

// ======================= helpers =======================
__device__ __forceinline__ uint32_t smem_u32(const void* p) {
    uint32_t a;
    asm("{ .reg .u64 t; cvta.to.shared.u64 t, %1; cvt.u32.u64 %0, t; }" : "=r"(a) : "l"(p));
    return a;
}

// Blocked SW128 atom layout for a [rows=128, K=128] 16-bit tile.
__host__ __device__ __forceinline__ uint32_t blk_off(int row, int col /*elem idx*/) {
    uint32_t off = (uint32_t)((row >> 3) + (col >> 6) * 16) * 1024u
                 + (uint32_t)(row & 7) * 128u + (uint32_t)(col & 63) * 2u;
    return off ^ ((off >> 3) & 0x70u);
}

__device__ __forceinline__ void ldsm4(uint32_t* r, uint32_t addr) {
    asm volatile("ldmatrix.sync.aligned.m8n8.x4.shared.b16 {%0,%1,%2,%3}, [%4];"
                 : "=r"(r[0]), "=r"(r[1]), "=r"(r[2]), "=r"(r[3]) : "r"(addr));
}

__device__ __forceinline__ void mma_f16(float* d, const uint32_t* a,
                                        uint32_t b0, uint32_t b1) {
    asm volatile(
        "mma.sync.aligned.m16n8k16.row.col.f32.f16.f16.f32 "
        "{%0,%1,%2,%3}, {%4,%5,%6,%7}, {%8,%9}, {%0,%1,%2,%3};"
        : "+f"(d[0]), "+f"(d[1]), "+f"(d[2]), "+f"(d[3])
        : "r"(a[0]), "r"(a[1]), "r"(a[2]), "r"(a[3]), "r"(b0), "r"(b1));
}

// Per-block int64/int32 detection (first 64 entries).
__device__ __forceinline__ int block_is64(const void* p) {
    __shared__ int s64;
    if (threadIdx.x == 0) {
        const unsigned int* u = (const unsigned int*)p;
        int e = 1;
        #pragma unroll
        for (int i = 0; i < 64; i++)
            if (u[2 * i + 1] != 0u) e = 0;
        s64 = e;
    }
    __syncthreads();
    return s64;
}

__device__ __forceinline__ int ld_idx2(const void* p, long long i, int is64) {
    return is64 ? (int)((const long long*)p)[i] : ((const int*)p)[i];
}

// ======================= degree (detect fused) =======================
__global__ void deg_count(const void* __restrict__ ei, long long E) {
    int is64 = block_is64(ei);
    long long i = (long long)blockIdx.x * blockDim.x + threadIdx.x;
    if (i < E) atomicAdd(&g_deg[ld_idx2(ei, E + i, is64)], 1);
}

// ======================= scan phase 1 (+ dinv fused) =======================
__global__ void scan_partial(int n) {
    int i = blockIdx.x * 256 + threadIdx.x;
    int v = (i < n) ? g_deg[i] : 0;
    if (i < n) g_dinv[i] = rsqrtf((float)(v + 1));  // +1 self loop
    int s = v;
    #pragma unroll
    for (int o = 16; o; o >>= 1) s += __shfl_down_sync(0xffffffffu, s, o);
    __shared__ int ws[8];
    if ((threadIdx.x & 31) == 0) ws[threadIdx.x >> 5] = s;
    __syncthreads();
    if (threadIdx.x == 0) {
        int t = 0;
        #pragma unroll
        for (int k = 0; k < 8; k++) t += ws[k];
        g_bsum[blockIdx.x] = t;
    }
}

// ======================= scan phase 2 (top-scan fused per block) =======================
__global__ void scan_final(int n, long long E) {
    int t = threadIdx.x, lane = t & 31, wid = t >> 5;

    __shared__ int s_off;
    {
        int part = 0;
        for (int i = t; i < blockIdx.x; i += 256) part += g_bsum[i];
        #pragma unroll
        for (int o = 16; o; o >>= 1) part += __shfl_down_sync(0xffffffffu, part, o);
        __shared__ int wr[8];
        if (lane == 0) wr[wid] = part;
        __syncthreads();
        if (t == 0) {
            int s = 0;
            #pragma unroll
            for (int k = 0; k < 8; k++) s += wr[k];
            s_off = s;
        }
        __syncthreads();
    }

    int i = blockIdx.x * 256 + t;
    int v = (i < n) ? g_deg[i] : 0;
    int incl = v;
    #pragma unroll
    for (int o = 1; o < 32; o <<= 1) {
        int u = __shfl_up_sync(0xffffffffu, incl, o);
        if (lane >= o) incl += u;
    }
    __shared__ int ws[8], wso[8];
    if (lane == 31) ws[wid] = incl;
    __syncthreads();
    if (t == 0) {
        int s = 0;
        #pragma unroll
        for (int k = 0; k < 8; k++) { wso[k] = s; s += ws[k]; }
    }
    __syncthreads();
    int excl = incl - v + wso[wid] + s_off;
    if (i < n) { g_rowptr[i] = excl; g_cursor[i] = excl; }
    if (i == n - 1) g_rowptr[n] = (int)E;
}

__global__ void fill_kernel(const void* __restrict__ ei, long long E) {
    int is64 = block_is64(ei);
    long long i = (long long)blockIdx.x * blockDim.x + threadIdx.x;
    if (i >= E) return;
    int s = ld_idx2(ei, i, is64);
    int d = ld_idx2(ei, E + i, is64);
    int pos = atomicAdd(&g_cursor[d], 1);
    g_csrc[pos] = s;
}

// ======================= W transpose into swizzled fp16 images =======================
__global__ void wprep(const float* __restrict__ W1, const float* __restrict__ W2,
                      uint32_t* __restrict__ img) {
    int i = blockIdx.x * 256 + threadIdx.x;      // 2 layers * 128 n * 64 k2
    if (i >= 16384) return;
    int l = i >> 13, rem = i & 8191;
    int nrow = rem >> 6, k2 = rem & 63;
    const float* W = l ? W2 : W1;
    float x0 = W[(2 * k2) * 128 + nrow];
    float x1 = W[(2 * k2 + 1) * 128 + nrow];
    __half2 hv = __floats2half2_rn(x0, x1);      // low = even col
    uint32_t widx = blk_off(nrow, 2 * k2) >> 2;
    img[l * 8192 + widx] = *(uint32_t*)&hv;
}

// ======================= R10-style HMMA GEMM (gemm1): outA = fp16((X@W1)*dinv) =======================
#define SM_A 0
#define SM_B 32768
#define GEMM_SMEM 65536

__global__ void __launch_bounds__(256, 2)
gemm_tc(const float* __restrict__ X, const uint32_t* __restrict__ Wimg,
        __half* __restrict__ outA, int n) {
    extern __shared__ char sm[];
    uint32_t smem_base = smem_u32(sm);
    int t = threadIdx.x;
    int w = t >> 5, lane = t & 31;
    int row0 = blockIdx.x * 128;

    // ---- stage X tile (fp32 -> fp16) into blocked+swizzled SMEM ----
    {
        int lrow = t >> 1;
        int kh = t & 1;
        int row = row0 + lrow;
        #pragma unroll 4
        for (int i = 0; i < 16; i++) {
            int k = kh * 64 + i * 4;
            float4 v = (row < n) ? ((const float4*)X)[(size_t)row * 32 + kh * 16 + i]
                                 : make_float4(0.f, 0.f, 0.f, 0.f);
            __half2 p0 = __floats2half2_rn(v.x, v.y);
            __half2 p1 = __floats2half2_rn(v.z, v.w);
            *(uint32_t*)(sm + SM_A + blk_off(lrow, k))     = *(uint32_t*)&p0;
            *(uint32_t*)(sm + SM_A + blk_off(lrow, k + 2)) = *(uint32_t*)&p1;
        }
    }
    // ---- copy W image (32KB) ----
    {
        const uint4* s4 = (const uint4*)Wimg;
        uint4* d4 = (uint4*)(sm + SM_B);
        #pragma unroll
        for (int i = 0; i < 8; i++) d4[t + 256 * i] = s4[t + 256 * i];
    }
    __syncthreads();

    int mwarp = (w & 3) * 32;
    int nwarp = (w >> 2) * 64;

    float acc[2][8][4];
    #pragma unroll
    for (int mi = 0; mi < 2; mi++)
        #pragma unroll
        for (int nj = 0; nj < 8; nj++)
            #pragma unroll
            for (int q = 0; q < 4; q++) acc[mi][nj][q] = 0.f;

    int a_row = mwarp + (lane & 15);
    int a_kof = (lane >> 4) << 3;
    int b_row = nwarp + (lane & 7) + ((lane >> 4) << 3);
    int b_kof = (lane & 8);

    uint32_t Abase = smem_base + SM_A;
    uint32_t Bbase = smem_base + SM_B;

    #pragma unroll
    for (int ks = 0; ks < 8; ks++) {
        int k0 = ks * 16;
        uint32_t a[2][4];
        ldsm4(a[0], Abase + blk_off(a_row,      k0 + a_kof));
        ldsm4(a[1], Abase + blk_off(a_row + 16, k0 + a_kof));
        uint32_t b[4][4];
        #pragma unroll
        for (int g = 0; g < 4; g++)
            ldsm4(b[g], Bbase + blk_off(b_row + g * 16, k0 + b_kof));
        #pragma unroll
        for (int mi = 0; mi < 2; mi++)
            #pragma unroll
            for (int g = 0; g < 4; g++) {
                mma_f16(acc[mi][2 * g],     a[mi], b[g][0], b[g][1]);
                mma_f16(acc[mi][2 * g + 1], a[mi], b[g][2], b[g][3]);
            }
    }

    // ---- epilogue: msg = h * dinv[row] ----
    {
        int g = lane >> 2, i2 = lane & 3;
        #pragma unroll
        for (int mi = 0; mi < 2; mi++) {
            int r0 = row0 + mwarp + mi * 16 + g;
            int r1 = r0 + 8;
            float s0 = (r0 < n) ? g_dinv[r0] : 0.f;
            float s1 = (r1 < n) ? g_dinv[r1] : 0.f;
            #pragma unroll
            for (int nj = 0; nj < 8; nj++) {
                int c = nwarp + nj * 8 + 2 * i2;
                if (r0 < n)
                    *(__half2*)(outA + (size_t)r0 * 128 + c) =
                        __floats2half2_rn(acc[mi][nj][0] * s0, acc[mi][nj][1] * s0);
                if (r1 < n)
                    *(__half2*)(outA + (size_t)r1 * 128 + c) =
                        __floats2half2_rn(acc[mi][nj][2] * s1, acc[mi][nj][3] * s1);
            }
        }
    }
}

// ======================= FUSED gather1 + gemm2 =======================
// Phase 1: 8 warps x 16 nodes: gather prescaled msgs (pA) -> z1 (dinv*acc+bias, relu)
//          -> fp16 into swizzled SMEM A-tile.
// Phase 2: R10 MMA mainloop (A from SMEM, W2 image) -> layer-2 msgs (dinv-scaled) to outC.
__global__ void __launch_bounds__(256, 2)
fused_gg(const __half* __restrict__ A, const uint32_t* __restrict__ Wimg,
         const float* __restrict__ bias, __half* __restrict__ outC, int n) {
    extern __shared__ char sm[];
    uint32_t smem_base = smem_u32(sm);
    int t = threadIdx.x;
    int w = t >> 5, lane = t & 31;
    int row0 = blockIdx.x * 128;

    // ---- copy W2 image (32KB) ----
    {
        const uint4* s4 = (const uint4*)Wimg;
        uint4* d4 = (uint4*)(sm + SM_B);
        #pragma unroll
        for (int i = 0; i < 8; i++) d4[t + 256 * i] = s4[t + 256 * i];
    }

    // ---- phase 1: gather 16 nodes per warp into SMEM A-tile ----
    {
        const uint2* A2 = (const uint2*)A;
        float4 bb = ((const float4*)bias)[lane];
        for (int i = 0; i < 16; i++) {
            int lrow = w * 16 + i;
            int node = row0 + lrow;
            float4 o = make_float4(0.f, 0.f, 0.f, 0.f);
            if (node < n) {
                int beg = g_rowptr[node], end = g_rowptr[node + 1];
                float4 acc;
                {
                    uint2 u = A2[(size_t)node * 32 + lane];   // self msg
                    float2 p0 = __half22float2(*(const __half2*)&u.x);
                    float2 p1 = __half22float2(*(const __half2*)&u.y);
                    acc.x = p0.x; acc.y = p0.y; acc.z = p1.x; acc.w = p1.y;
                }
                for (int j0 = beg; j0 < end; j0 += 32) {
                    int m = min(32, end - j0);
                    int idx = (lane < m) ? g_csrc[j0 + lane] : 0;
                    int k = 0;
                    for (; k + 8 <= m; k += 8) {
                        uint2 v[8];
                        #pragma unroll
                        for (int p = 0; p < 8; p++) {
                            int s = __shfl_sync(0xffffffffu, idx, k + p);
                            v[p] = A2[(size_t)s * 32 + lane];
                        }
                        #pragma unroll
                        for (int p = 0; p < 8; p++) {
                            float2 p0 = __half22float2(*(const __half2*)&v[p].x);
                            float2 p1 = __half22float2(*(const __half2*)&v[p].y);
                            acc.x += p0.x; acc.y += p0.y; acc.z += p1.x; acc.w += p1.y;
                        }
                    }
                    for (; k < m; k++) {
                        int s = __shfl_sync(0xffffffffu, idx, k);
                        uint2 u = A2[(size_t)s * 32 + lane];
                        float2 p0 = __half22float2(*(const __half2*)&u.x);
                        float2 p1 = __half22float2(*(const __half2*)&u.y);
                        acc.x += p0.x; acc.y += p0.y; acc.z += p1.x; acc.w += p1.y;
                    }
                }
                float sc = g_dinv[node];
                o.x = fmaxf(fmaf(acc.x, sc, bb.x), 0.f);
                o.y = fmaxf(fmaf(acc.y, sc, bb.y), 0.f);
                o.z = fmaxf(fmaf(acc.z, sc, bb.z), 0.f);
                o.w = fmaxf(fmaf(acc.w, sc, bb.w), 0.f);
            }
            __half2 h0 = __floats2half2_rn(o.x, o.y);
            __half2 h1 = __floats2half2_rn(o.z, o.w);
            uint2 pk = make_uint2(*(uint32_t*)&h0, *(uint32_t*)&h1);
            *(uint2*)(sm + SM_A + blk_off(lrow, 4 * lane)) = pk;
        }
    }
    __syncthreads();

    // ---- phase 2: MMA z1 @ W2 ----
    int mwarp = (w & 3) * 32;
    int nwarp = (w >> 2) * 64;

    float acc[2][8][4];
    #pragma unroll
    for (int mi = 0; mi < 2; mi++)
        #pragma unroll
        for (int nj = 0; nj < 8; nj++)
            #pragma unroll
            for (int q = 0; q < 4; q++) acc[mi][nj][q] = 0.f;

    int a_row = mwarp + (lane & 15);
    int a_kof = (lane >> 4) << 3;
    int b_row = nwarp + (lane & 7) + ((lane >> 4) << 3);
    int b_kof = (lane & 8);

    uint32_t Abase = smem_base + SM_A;
    uint32_t Bbase = smem_base + SM_B;

    #pragma unroll
    for (int ks = 0; ks < 8; ks++) {
        int k0 = ks * 16;
        uint32_t a[2][4];
        ldsm4(a[0], Abase + blk_off(a_row,      k0 + a_kof));
        ldsm4(a[1], Abase + blk_off(a_row + 16, k0 + a_kof));
        uint32_t b[4][4];
        #pragma unroll
        for (int g = 0; g < 4; g++)
            ldsm4(b[g], Bbase + blk_off(b_row + g * 16, k0 + b_kof));
        #pragma unroll
        for (int mi = 0; mi < 2; mi++)
            #pragma unroll
            for (int g = 0; g < 4; g++) {
                mma_f16(acc[mi][2 * g],     a[mi], b[g][0], b[g][1]);
                mma_f16(acc[mi][2 * g + 1], a[mi], b[g][2], b[g][3]);
            }
    }

    // ---- epilogue: layer-2 msg = h2 * dinv[row] ----
    {
        int g = lane >> 2, i2 = lane & 3;
        #pragma unroll
        for (int mi = 0; mi < 2; mi++) {
            int r0 = row0 + mwarp + mi * 16 + g;
            int r1 = r0 + 8;
            float s0 = (r0 < n) ? g_dinv[r0] : 0.f;
            float s1 = (r1 < n) ? g_dinv[r1] : 0.f;
            #pragma unroll
            for (int nj = 0; nj < 8; nj++) {
                int c = nwarp + nj * 8 + 2 * i2;
                if (r0 < n)
                    *(__half2*)(outC + (size_t)r0 * 128 + c) =
                        __floats2half2_rn(acc[mi][nj][0] * s0, acc[mi][nj][1] * s0);
                if (r1 < n)
                    *(__half2*)(outC + (size_t)r1 * 128 + c) =
                        __floats2half2_rn(acc[mi][nj][2] * s1, acc[mi][nj][3] * s1);
            }
        }
    }
}

// ======================= CSR gather (prescaled fp16 messages) =======================
__global__ void gather_kernel(const __half* __restrict__ A, __half* __restrict__ B,
                              const float* __restrict__ bias, int n, int relu) {
    int node = blockIdx.x * (blockDim.x >> 5) + (threadIdx.x >> 5);
    int lane = threadIdx.x & 31;
    if (node >= n) return;
    int beg = g_rowptr[node], end = g_rowptr[node + 1];
    const uint2* A2 = (const uint2*)A;

    float4 acc;
    {
        uint2 u = A2[(size_t)node * 32 + lane];   // self msg
        float2 p0 = __half22float2(*(const __half2*)&u.x);
        float2 p1 = __half22float2(*(const __half2*)&u.y);
        acc.x = p0.x; acc.y = p0.y; acc.z = p1.x; acc.w = p1.y;
    }

    for (int j0 = beg; j0 < end; j0 += 32) {
        int m = min(32, end - j0);
        int idx = (lane < m) ? g_csrc[j0 + lane] : 0;
        int k = 0;
        for (; k + 8 <= m; k += 8) {
            uint2 v[8];
            #pragma unroll
            for (int p = 0; p < 8; p++) {
                int s = __shfl_sync(0xffffffffu, idx, k + p);
                v[p] = A2[(size_t)s * 32 + lane];
            }
            #pragma unroll
            for (int p = 0; p < 8; p++) {
                float2 p0 = __half22float2(*(const __half2*)&v[p].x);
                float2 p1 = __half22float2(*(const __half2*)&v[p].y);
                acc.x += p0.x; acc.y += p0.y; acc.z += p1.x; acc.w += p1.y;
            }
        }
        for (; k < m; k++) {
            int s = __shfl_sync(0xffffffffu, idx, k);
            uint2 u = A2[(size_t)s * 32 + lane];
            float2 p0 = __half22float2(*(const __half2*)&u.x);
            float2 p1 = __half22float2(*(const __half2*)&u.y);
            acc.x += p0.x; acc.y += p0.y; acc.z += p1.x; acc.w += p1.y;
        }
    }

    float sc = g_dinv[node];
    float4 bb = ((const float4*)bias)[lane];
    float4 o;
    o.x = fmaf(acc.x, sc, bb.x);
    o.y = fmaf(acc.y, sc, bb.y);
    o.z = fmaf(acc.z, sc, bb.z);
    o.w = fmaf(acc.w, sc, bb.w);
    if (relu) {
        o.x = fmaxf(o.x, 0.f); o.y = fmaxf(o.y, 0.f);
        o.z = fmaxf(o.z, 0.f); o.w = fmaxf(o.w, 0.f);
    }
    __half2 h0 = __floats2half2_rn(o.x, o.y);
    __half2 h1 = __floats2half2_rn(o.z, o.w);
    uint2 ov = make_uint2(*(uint32_t*)&h0, *(uint32_t*)&h1);
    ((uint2*)B)[(size_t)node * 32 + lane] = ov;
}

// ======================= decode (fp16 z, detect fused) =======================
__global__ void decode_kernel(const void* __restrict__ eli, long long M,
                              const __half* __restrict__ Z, float* __restrict__ out) {
    int is64 = block_is64(eli);
    long long w = (long long)blockIdx.x * (blockDim.x >> 5) + (threadIdx.x >> 5);
    int lane = threadIdx.x & 31;
    if (w >= M) return;
    int s = 0, d = 0;
    if (lane == 0) {
        s = ld_idx2(eli, w, is64);
        d = ld_idx2(eli, M + w, is64);
    }
    s = __shfl_sync(0xffffffffu, s, 0);
    d = __shfl_sync(0xffffffffu, d, 0);
    const uint2* Z2 = (const uint2*)Z;
    uint2 ua = Z2[(size_t)s * 32 + lane];
    uint2 ub = Z2[(size_t)d * 32 + lane];
    float2 a0 = __half22float2(*(const __half2*)&ua.x);
    float2 a1 = __half22float2(*(const __half2*)&ua.y);
    float2 b0 = __half22float2(*(const __half2*)&ub.x);
    float2 b1 = __half22float2(*(const __half2*)&ub.y);
    float sum = a0.x * b0.x + a0.y * b0.y + a1.x * b1.x + a1.y * b1.y;
    #pragma unroll
    for (int o = 16; o; o >>= 1) sum += __shfl_xor_sync(0xffffffffu, sum, o);
    if (lane == 0) out[w] = sum;
}

// ======================= launch =======================
extern "C" void kernel_launch(void* const* d_in, const int* in_sizes, int n_in,
                              void* d_out, int out_size) {
    const float* x   = (const float*)d_in[0];
    const void*  ei  = d_in[1];
    const void*  eli = d_in[2];
    const float* W1  = (const float*)d_in[3];
    const float* b1  = (const float*)d_in[4];
    const float* W2  = (const float*)d_in[5];
    const float* b2  = (const float*)d_in[6];
    float* out = (float*)d_out;

    int n = in_sizes[0] / DIM;
    long long E = in_sizes[1] / 2;
    long long M = in_sizes[2] / 2;

    __half *pA = nullptr, *pB = nullptr, *pC = nullptr;
    uint32_t* pW = nullptr;
    int* pDeg = nullptr;
    cudaGetSymbolAddress((void**)&pA, g_bufA);
    cudaGetSymbolAddress((void**)&pB, g_bufB);
    cudaGetSymbolAddress((void**)&pC, g_bufC);
    cudaGetSymbolAddress((void**)&pW, g_Wimg);
    cudaGetSymbolAddress((void**)&pDeg, g_deg);
    cudaFuncSetAttribute(gemm_tc, cudaFuncAttributeMaxDynamicSharedMemorySize, GEMM_SMEM);
    cudaFuncSetAttribute(fused_gg, cudaFuncAttributeMaxDynamicSharedMemorySize, GEMM_SMEM);

    // Optional side-stream: fall back to single-stream if creation fails.
    static cudaStream_t sB = nullptr;
    static cudaEvent_t evFork = nullptr, evDinv = nullptr, evJoin = nullptr;
    static int streamTried = 0;
    if (!streamTried) {
        streamTried = 1;
        bool ok = (cudaStreamCreateWithFlags(&sB, cudaStreamNonBlocking) == cudaSuccess);
        ok = ok && (cudaEventCreateWithFlags(&evFork, cudaEventDisableTiming) == cudaSuccess);
        ok = ok && (cudaEventCreateWithFlags(&evDinv, cudaEventDisableTiming) == cudaSuccess);
        ok = ok && (cudaEventCreateWithFlags(&evJoin, cudaEventDisableTiming) == cudaSuccess);
        if (!ok) sB = nullptr;
        cudaGetLastError();
    }
    cudaStream_t sP = sB ? sB : (cudaStream_t)0;

    int nb256 = (n + 255) / 256;
    int eb    = (int)((E + 255) / 256);
    int mbw   = (int)((M + 7) / 8);
    int gbw   = (n + 7) / 8;
    int gemmb = (n + 127) / 128;

    // (1) wprep on default stream
    wprep<<<64, 256>>>(W1, W2, pW);

    // fork
    if (sB) {
        cudaEventRecord(evFork, 0);
        cudaStreamWaitEvent(sB, evFork, 0);
    }

    // preproc on sP: memset, deg_count, scan_partial [-> dinv ready]
    cudaMemsetAsync(pDeg, 0, (size_t)n * sizeof(int), sP);
    deg_count<<<eb, 256, 0, sP>>>(ei, E);
    scan_partial<<<nb256, 256, 0, sP>>>(n);
    if (sB) cudaEventRecord(evDinv, sB);

    // gemm1 on default stream (epilogue needs dinv)
    if (sB) cudaStreamWaitEvent(0, evDinv, 0);
    gemm_tc<<<gemmb, 256, GEMM_SMEM>>>(x, pW, pA, n);

    // scan_final + fill on sP
    scan_final<<<nb256, 256, 0, sP>>>(n, E);
    fill_kernel<<<eb, 256, 0, sP>>>(ei, E);
    if (sB) cudaEventRecord(evJoin, sB);

    // join
    if (sB) cudaStreamWaitEvent(0, evJoin, 0);

    // fused gather1+gemm2 (pA -> pC), then gather2 (pC -> pB), decode
    fused_gg<<<gemmb, 256, GEMM_SMEM>>>(pA, pW + 8192, b1, pC, n);
    gather_kernel<<<gbw, 256>>>(pC, pB, b2, n, 0);
    decode_kernel<<<mbw, 256>>>(eli, M, pB, out);
}

// round 16
// speedup vs baseline: 1.0693x; 1.0693x over previous
#include <cuda_runtime.h>
#include <cuda_bf16.h>
#include <cuda_fp16.h>
#include <math.h>
#include <stdint.h>

#define DIM 128
#define NMAX 100000
#define EMAX 2000000

// Scratch (allocation-free rule: __device__ globals)
__device__ __half   g_bufA[(size_t)NMAX * DIM];   // messages = h*dinv[src] (fp16)
__device__ __half   g_bufB[(size_t)NMAX * DIM];   // activations / final z (fp16)
__device__ int      g_deg[NMAX];
__device__ float    g_dinv[NMAX];
__device__ int      g_rowptr[NMAX + 1];
__device__ int      g_cursor[NMAX];
__device__ int      g_csrc[EMAX];
__device__ int      g_bsum[512];
__device__ uint32_t g_Wimg[2][8192];              // [layer][swizzled fp16x2 image]

// ======================= helpers =======================
__device__ __forceinline__ uint32_t smem_u32(const void* p) {
    uint32_t a;
    asm("{ .reg .u64 t; cvta.to.shared.u64 t, %1; cvt.u32.u64 %0, t; }" : "=r"(a) : "l"(p));
    return a;
}

// Blocked SW128 atom layout for a [rows=128, K=128] 16-bit tile.
__host__ __device__ __forceinline__ uint32_t blk_off(int row, int col /*elem idx*/) {
    uint32_t off = (uint32_t)((row >> 3) + (col >> 6) * 16) * 1024u
                 + (uint32_t)(row & 7) * 128u + (uint32_t)(col & 63) * 2u;
    return off ^ ((off >> 3) & 0x70u);
}

__device__ __forceinline__ void ldsm4(uint32_t* r, uint32_t addr) {
    asm volatile("ldmatrix.sync.aligned.m8n8.x4.shared.b16 {%0,%1,%2,%3}, [%4];"
                 : "=r"(r[0]), "=r"(r[1]), "=r"(r[2]), "=r"(r[3]) : "r"(addr));
}

__device__ __forceinline__ void mma_f16(float* d, const uint32_t* a,
                                        uint32_t b0, uint32_t b1) {
    asm volatile(
        "mma.sync.aligned.m16n8k16.row.col.f32.f16.f16.f32 "
        "{%0,%1,%2,%3}, {%4,%5,%6,%7}, {%8,%9}, {%0,%1,%2,%3};"
        : "+f"(d[0]), "+f"(d[1]), "+f"(d[2]), "+f"(d[3])
        : "r"(a[0]), "r"(a[1]), "r"(a[2]), "r"(a[3]), "r"(b0), "r"(b1));
}

// Per-block int64/int32 detection (first 64 entries).
__device__ __forceinline__ int block_is64(const void* p) {
    __shared__ int s64;
    if (threadIdx.x == 0) {
        const unsigned int* u = (const unsigned int*)p;
        int e = 1;
        #pragma unroll
        for (int i = 0; i < 64; i++)
            if (u[2 * i + 1] != 0u) e = 0;
        s64 = e;
    }
    __syncthreads();
    return s64;
}

__device__ __forceinline__ int ld_idx2(const void* p, long long i, int is64) {
    return is64 ? (int)((const long long*)p)[i] : ((const int*)p)[i];
}

// ======================= degree (detect fused) =======================
__global__ void deg_count(const void* __restrict__ ei, long long E) {
    int is64 = block_is64(ei);
    long long i = (long long)blockIdx.x * blockDim.x + threadIdx.x;
    if (i < E) atomicAdd(&g_deg[ld_idx2(ei, E + i, is64)], 1);
}

// ======================= scan phase 1 (+ dinv fused) =======================
__global__ void scan_partial(int n) {
    int i = blockIdx.x * 256 + threadIdx.x;
    int v = (i < n) ? g_deg[i] : 0;
    if (i < n) g_dinv[i] = rsqrtf((float)(v + 1));  // +1 self loop
    int s = v;
    #pragma unroll
    for (int o = 16; o; o >>= 1) s += __shfl_down_sync(0xffffffffu, s, o);
    __shared__ int ws[8];
    if ((threadIdx.x & 31) == 0) ws[threadIdx.x >> 5] = s;
    __syncthreads();
    if (threadIdx.x == 0) {
        int t = 0;
        #pragma unroll
        for (int k = 0; k < 8; k++) t += ws[k];
        g_bsum[blockIdx.x] = t;
    }
}

// ======================= scan phase 2 (top-scan fused per block) =======================
__global__ void scan_final(int n, long long E) {
    int t = threadIdx.x, lane = t & 31, wid = t >> 5;

    __shared__ int s_off;
    {
        int part = 0;
        for (int i = t; i < blockIdx.x; i += 256) part += g_bsum[i];
        #pragma unroll
        for (int o = 16; o; o >>= 1) part += __shfl_down_sync(0xffffffffu, part, o);
        __shared__ int wr[8];
        if (lane == 0) wr[wid] = part;
        __syncthreads();
        if (t == 0) {
            int s = 0;
            #pragma unroll
            for (int k = 0; k < 8; k++) s += wr[k];
            s_off = s;
        }
        __syncthreads();
    }

    int i = blockIdx.x * 256 + t;
    int v = (i < n) ? g_deg[i] : 0;
    int incl = v;
    #pragma unroll
    for (int o = 1; o < 32; o <<= 1) {
        int u = __shfl_up_sync(0xffffffffu, incl, o);
        if (lane >= o) incl += u;
    }
    __shared__ int ws[8], wso[8];
    if (lane == 31) ws[wid] = incl;
    __syncthreads();
    if (t == 0) {
        int s = 0;
        #pragma unroll
        for (int k = 0; k < 8; k++) { wso[k] = s; s += ws[k]; }
    }
    __syncthreads();
    int excl = incl - v + wso[wid] + s_off;
    if (i < n) { g_rowptr[i] = excl; g_cursor[i] = excl; }
    if (i == n - 1) g_rowptr[n] = (int)E;
}

__global__ void fill_kernel(const void* __restrict__ ei, long long E) {
    int is64 = block_is64(ei);
    long long i = (long long)blockIdx.x * blockDim.x + threadIdx.x;
    if (i >= E) return;
    int s = ld_idx2(ei, i, is64);
    int d = ld_idx2(ei, E + i, is64);
    int pos = atomicAdd(&g_cursor[d], 1);
    g_csrc[pos] = s;
}

// ======================= W transpose into swizzled fp16 images (+ deg zero) =======================
__global__ void wprep(const float* __restrict__ W1, const float* __restrict__ W2,
                      uint32_t* __restrict__ img, int n) {
    int i = blockIdx.x * 256 + threadIdx.x;      // 16384 threads
    // zero g_deg (replaces the memset launch)
    for (int j = i; j < n; j += 16384) g_deg[j] = 0;
    if (i >= 16384) return;
    int l = i >> 13, rem = i & 8191;
    int nrow = rem >> 6, k2 = rem & 63;
    const float* W = l ? W2 : W1;
    float x0 = W[(2 * k2) * 128 + nrow];
    float x1 = W[(2 * k2 + 1) * 128 + nrow];
    __half2 hv = __floats2half2_rn(x0, x1);      // low = even col
    uint32_t widx = blk_off(nrow, 2 * k2) >> 2;
    img[l * 8192 + widx] = *(uint32_t*)&hv;
}

// ======================= HMMA GEMM: outA = fp16((X @ W) * dinv[row]) =======================
// FP16IN=false: X is fp32 [n,128]; FP16IN=true: X is fp16 [n,128].
#define SM_A 0
#define SM_B 32768
#define GEMM_SMEM 65536

template<bool FP16IN>
__global__ void __launch_bounds__(256, 2)
gemm_tc(const void* __restrict__ Xv, const uint32_t* __restrict__ Wimg,
        __half* __restrict__ outA, int n) {
    extern __shared__ char sm[];
    uint32_t smem_base = smem_u32(sm);
    int t = threadIdx.x;
    int w = t >> 5, lane = t & 31;
    int row0 = blockIdx.x * 128;

    // ---- load X tile into blocked+swizzled SMEM (fp16) ----
    {
        int lrow = t >> 1;
        int kh = t & 1;
        int row = row0 + lrow;
        #pragma unroll 4
        for (int i = 0; i < 16; i++) {
            int k = kh * 64 + i * 4;
            uint32_t u0, u1;
            if (FP16IN) {
                uint2 v = (row < n) ? ((const uint2*)Xv)[(size_t)row * 32 + kh * 16 + i]
                                    : make_uint2(0u, 0u);
                u0 = v.x; u1 = v.y;
            } else {
                float4 v = (row < n) ? ((const float4*)Xv)[(size_t)row * 32 + kh * 16 + i]
                                     : make_float4(0.f, 0.f, 0.f, 0.f);
                __half2 p0 = __floats2half2_rn(v.x, v.y);
                __half2 p1 = __floats2half2_rn(v.z, v.w);
                u0 = *(uint32_t*)&p0; u1 = *(uint32_t*)&p1;
            }
            *(uint32_t*)(sm + SM_A + blk_off(lrow, k))     = u0;
            *(uint32_t*)(sm + SM_A + blk_off(lrow, k + 2)) = u1;
        }
    }
    // ---- copy pre-swizzled W image (32KB) ----
    {
        const uint4* s4 = (const uint4*)Wimg;
        uint4* d4 = (uint4*)(sm + SM_B);
        #pragma unroll
        for (int i = 0; i < 8; i++) d4[t + 256 * i] = s4[t + 256 * i];
    }
    __syncthreads();

    int mwarp = (w & 3) * 32;
    int nwarp = (w >> 2) * 64;

    float acc[2][8][4];
    #pragma unroll
    for (int mi = 0; mi < 2; mi++)
        #pragma unroll
        for (int nj = 0; nj < 8; nj++)
            #pragma unroll
            for (int q = 0; q < 4; q++) acc[mi][nj][q] = 0.f;

    int a_row = mwarp + (lane & 15);
    int a_kof = (lane >> 4) << 3;
    int b_row = nwarp + (lane & 7) + ((lane >> 4) << 3);
    int b_kof = (lane & 8);

    uint32_t Abase = smem_base + SM_A;
    uint32_t Bbase = smem_base + SM_B;

    #pragma unroll
    for (int ks = 0; ks < 8; ks++) {
        int k0 = ks * 16;
        uint32_t a[2][4];
        ldsm4(a[0], Abase + blk_off(a_row,      k0 + a_kof));
        ldsm4(a[1], Abase + blk_off(a_row + 16, k0 + a_kof));
        uint32_t b[4][4];
        #pragma unroll
        for (int g = 0; g < 4; g++)
            ldsm4(b[g], Bbase + blk_off(b_row + g * 16, k0 + b_kof));
        #pragma unroll
        for (int mi = 0; mi < 2; mi++)
            #pragma unroll
            for (int g = 0; g < 4; g++) {
                mma_f16(acc[mi][2 * g],     a[mi], b[g][0], b[g][1]);
                mma_f16(acc[mi][2 * g + 1], a[mi], b[g][2], b[g][3]);
            }
    }

    // ---- epilogue: store msg = h * dinv[row] as fp16 ----
    {
        int g = lane >> 2, i2 = lane & 3;
        #pragma unroll
        for (int mi = 0; mi < 2; mi++) {
            int r0 = row0 + mwarp + mi * 16 + g;
            int r1 = r0 + 8;
            float s0 = (r0 < n) ? g_dinv[r0] : 0.f;
            float s1 = (r1 < n) ? g_dinv[r1] : 0.f;
            #pragma unroll
            for (int nj = 0; nj < 8; nj++) {
                int c = nwarp + nj * 8 + 2 * i2;
                if (r0 < n)
                    *(__half2*)(outA + (size_t)r0 * 128 + c) =
                        __floats2half2_rn(acc[mi][nj][0] * s0, acc[mi][nj][1] * s0);
                if (r1 < n)
                    *(__half2*)(outA + (size_t)r1 * 128 + c) =
                        __floats2half2_rn(acc[mi][nj][2] * s1, acc[mi][nj][3] * s1);
            }
        }
    }
}

// ======================= CSR gather (prescaled fp16 msgs, 16-deep MLP batches) =======================
__global__ void gather_kernel(const __half* __restrict__ A, __half* __restrict__ B,
                              const float* __restrict__ bias, int n, int relu) {
    int node = blockIdx.x * (blockDim.x >> 5) + (threadIdx.x >> 5);
    int lane = threadIdx.x & 31;
    if (node >= n) return;
    int beg = g_rowptr[node], end = g_rowptr[node + 1];
    const uint2* A2 = (const uint2*)A;   // 32 uint2 per row

    float4 acc;
    {
        uint2 u = A2[(size_t)node * 32 + lane];   // self msg (already * dinv)
        float2 p0 = __half22float2(*(const __half2*)&u.x);
        float2 p1 = __half22float2(*(const __half2*)&u.y);
        acc.x = p0.x; acc.y = p0.y; acc.z = p1.x; acc.w = p1.y;
    }

    for (int j0 = beg; j0 < end; j0 += 32) {
        int m = min(32, end - j0);
        int idx = (lane < m) ? g_csrc[j0 + lane] : 0;
        int k = 0;
        for (; k + 16 <= m; k += 16) {
            uint2 v[16];
            #pragma unroll
            for (int p = 0; p < 16; p++) {
                int s = __shfl_sync(0xffffffffu, idx, k + p);
                v[p] = A2[(size_t)s * 32 + lane];
            }
            #pragma unroll
            for (int p = 0; p < 16; p++) {
                float2 p0 = __half22float2(*(const __half2*)&v[p].x);
                float2 p1 = __half22float2(*(const __half2*)&v[p].y);
                acc.x += p0.x; acc.y += p0.y; acc.z += p1.x; acc.w += p1.y;
            }
        }
        for (; k + 4 <= m; k += 4) {
            uint2 v[4];
            #pragma unroll
            for (int p = 0; p < 4; p++) {
                int s = __shfl_sync(0xffffffffu, idx, k + p);
                v[p] = A2[(size_t)s * 32 + lane];
            }
            #pragma unroll
            for (int p = 0; p < 4; p++) {
                float2 p0 = __half22float2(*(const __half2*)&v[p].x);
                float2 p1 = __half22float2(*(const __half2*)&v[p].y);
                acc.x += p0.x; acc.y += p0.y; acc.z += p1.x; acc.w += p1.y;
            }
        }
        for (; k < m; k++) {
            int s = __shfl_sync(0xffffffffu, idx, k);
            uint2 u = A2[(size_t)s * 32 + lane];
            float2 p0 = __half22float2(*(const __half2*)&u.x);
            float2 p1 = __half22float2(*(const __half2*)&u.y);
            acc.x += p0.x; acc.y += p0.y; acc.z += p1.x; acc.w += p1.y;
        }
    }

    float sc = g_dinv[node];
    float4 bb = ((const float4*)bias)[lane];
    float4 o;
    o.x = fmaf(acc.x, sc, bb.x);
    o.y = fmaf(acc.y, sc, bb.y);
    o.z = fmaf(acc.z, sc, bb.z);
    o.w = fmaf(acc.w, sc, bb.w);
    if (relu) {
        o.x = fmaxf(o.x, 0.f); o.y = fmaxf(o.y, 0.f);
        o.z = fmaxf(o.z, 0.f); o.w = fmaxf(o.w, 0.f);
    }
    __half2 h0 = __floats2half2_rn(o.x, o.y);
    __half2 h1 = __floats2half2_rn(o.z, o.w);
    uint2 ov = make_uint2(*(uint32_t*)&h0, *(uint32_t*)&h1);
    ((uint2*)B)[(size_t)node * 32 + lane] = ov;
}

// ======================= decode (fp16 z, detect fused) =======================
__global__ void decode_kernel(const void* __restrict__ eli, long long M,
                              const __half* __restrict__ Z, float* __restrict__ out) {
    int is64 = block_is64(eli);
    long long w = (long long)blockIdx.x * (blockDim.x >> 5) + (threadIdx.x >> 5);
    int lane = threadIdx.x & 31;
    if (w >= M) return;
    int s = 0, d = 0;
    if (lane == 0) {
        s = ld_idx2(eli, w, is64);
        d = ld_idx2(eli, M + w, is64);
    }
    s = __shfl_sync(0xffffffffu, s, 0);
    d = __shfl_sync(0xffffffffu, d, 0);
    const uint2* Z2 = (const uint2*)Z;
    uint2 ua = Z2[(size_t)s * 32 + lane];
    uint2 ub = Z2[(size_t)d * 32 + lane];
    float2 a0 = __half22float2(*(const __half2*)&ua.x);
    float2 a1 = __half22float2(*(const __half2*)&ua.y);
    float2 b0 = __half22float2(*(const __half2*)&ub.x);
    float2 b1 = __half22float2(*(const __half2*)&ub.y);
    float sum = a0.x * b0.x + a0.y * b0.y + a1.x * b1.x + a1.y * b1.y;
    #pragma unroll
    for (int o = 16; o; o >>= 1) sum += __shfl_xor_sync(0xffffffffu, sum, o);
    if (lane == 0) out[w] = sum;
}

// ======================= launch =======================
extern "C" void kernel_launch(void* const* d_in, const int* in_sizes, int n_in,
                              void* d_out, int out_size) {
    const float* x   = (const float*)d_in[0];
    const void*  ei  = d_in[1];
    const void*  eli = d_in[2];
    const float* W1  = (const float*)d_in[3];
    const float* b1  = (const float*)d_in[4];
    const float* W2  = (const float*)d_in[5];
    const float* b2  = (const float*)d_in[6];
    float* out = (float*)d_out;

    int n = in_sizes[0] / DIM;
    long long E = in_sizes[1] / 2;
    long long M = in_sizes[2] / 2;

    __half *pA = nullptr, *pB = nullptr;
    uint32_t* pW = nullptr;
    cudaGetSymbolAddress((void**)&pA, g_bufA);
    cudaGetSymbolAddress((void**)&pB, g_bufB);
    cudaGetSymbolAddress((void**)&pW, g_Wimg);
    cudaFuncSetAttribute(gemm_tc<false>, cudaFuncAttributeMaxDynamicSharedMemorySize, GEMM_SMEM);
    cudaFuncSetAttribute(gemm_tc<true>,  cudaFuncAttributeMaxDynamicSharedMemorySize, GEMM_SMEM);

    // Optional side-stream: fall back to single-stream if creation fails.
    static cudaStream_t sB = nullptr;
    static cudaEvent_t evFork = nullptr, evDinv = nullptr, evJoin = nullptr;
    static int streamTried = 0;
    if (!streamTried) {
        streamTried = 1;
        bool ok = (cudaStreamCreateWithFlags(&sB, cudaStreamNonBlocking) == cudaSuccess);
        ok = ok && (cudaEventCreateWithFlags(&evFork, cudaEventDisableTiming) == cudaSuccess);
        ok = ok && (cudaEventCreateWithFlags(&evDinv, cudaEventDisableTiming) == cudaSuccess);
        ok = ok && (cudaEventCreateWithFlags(&evJoin, cudaEventDisableTiming) == cudaSuccess);
        if (!ok) sB = nullptr;
        cudaGetLastError();
    }
    cudaStream_t sP = sB ? sB : (cudaStream_t)0;

    int nb256 = (n + 255) / 256;
    int eb    = (int)((E + 255) / 256);
    int mbw   = (int)((M + 7) / 8);
    int gbw   = (n + 7) / 8;
    int gemmb = (n + 127) / 128;

    // (1) wprep on default stream (also zeroes g_deg — replaces memset)
    wprep<<<64, 256>>>(W1, W2, pW, n);

    // fork (evFork after wprep: orders deg zeroing before deg_count)
    if (sB) {
        cudaEventRecord(evFork, 0);
        cudaStreamWaitEvent(sB, evFork, 0);
    }

    // preproc on sP: deg_count, scan_partial [-> dinv ready]
    deg_count<<<eb, 256, 0, sP>>>(ei, E);
    scan_partial<<<nb256, 256, 0, sP>>>(n);
    if (sB) cudaEventRecord(evDinv, sB);

    // gemm1 on default stream (epilogue needs dinv)
    if (sB) cudaStreamWaitEvent(0, evDinv, 0);
    gemm_tc<false><<<gemmb, 256, GEMM_SMEM>>>(x, pW, pA, n);

    // scan_final + fill on sP
    scan_final<<<nb256, 256, 0, sP>>>(n, E);
    fill_kernel<<<eb, 256, 0, sP>>>(ei, E);
    if (sB) cudaEventRecord(evJoin, sB);

    // join
    if (sB) cudaStreamWaitEvent(0, evJoin, 0);

    // serial tail: gather1, gemm2, gather2, decode
    gather_kernel<<<gbw, 256>>>(pA, pB, b1, n, 1);
    gemm_tc<true><<<gemmb, 256, GEMM_SMEM>>>(pB, pW + 8192, pA, n);
    gather_kernel<<<gbw, 256>>>(pA, pB, b2, n, 0);
    decode_kernel<<<mbw, 256>>>(eli, M, pB, out);
}

// round 17
// speedup vs baseline: 1.1122x; 1.0402x over previous
#include <cuda_runtime.h>
#include <cuda_bf16.h>
#include <cuda_fp16.h>
#include <math.h>
#include <stdint.h>

#define DIM 128
#define NMAX 100000
#define EMAX 2000000

// Scratch (allocation-free rule: __device__ globals)
__device__ __half   g_bufA[(size_t)NMAX * DIM];   // messages = h*dinv[src] (fp16)
__device__ __half   g_bufB[(size_t)NMAX * DIM];   // activations / final z (fp16)
__device__ int      g_deg[NMAX];
__device__ float    g_dinv[NMAX];
__device__ int      g_rowptr[NMAX + 1];
__device__ int      g_cursor[NMAX];
__device__ int      g_csrc[EMAX];
__device__ int      g_bsum[512];
__device__ uint32_t g_Wimg[2][8192];              // [layer][swizzled fp16x2 image]

// ======================= helpers =======================
__device__ __forceinline__ uint32_t smem_u32(const void* p) {
    uint32_t a;
    asm("{ .reg .u64 t; cvta.to.shared.u64 t, %1; cvt.u32.u64 %0, t; }" : "=r"(a) : "l"(p));
    return a;
}

// Blocked SW128 atom layout for a [rows=128, K=128] 16-bit tile.
__host__ __device__ __forceinline__ uint32_t blk_off(int row, int col /*elem idx*/) {
    uint32_t off = (uint32_t)((row >> 3) + (col >> 6) * 16) * 1024u
                 + (uint32_t)(row & 7) * 128u + (uint32_t)(col & 63) * 2u;
    return off ^ ((off >> 3) & 0x70u);
}

__device__ __forceinline__ void ldsm4(uint32_t* r, uint32_t addr) {
    asm volatile("ldmatrix.sync.aligned.m8n8.x4.shared.b16 {%0,%1,%2,%3}, [%4];"
                 : "=r"(r[0]), "=r"(r[1]), "=r"(r[2]), "=r"(r[3]) : "r"(addr));
}

__device__ __forceinline__ void mma_f16(float* d, const uint32_t* a,
                                        uint32_t b0, uint32_t b1) {
    asm volatile(
        "mma.sync.aligned.m16n8k16.row.col.f32.f16.f16.f32 "
        "{%0,%1,%2,%3}, {%4,%5,%6,%7}, {%8,%9}, {%0,%1,%2,%3};"
        : "+f"(d[0]), "+f"(d[1]), "+f"(d[2]), "+f"(d[3])
        : "r"(a[0]), "r"(a[1]), "r"(a[2]), "r"(a[3]), "r"(b0), "r"(b1));
}

// Per-block int64/int32 detection (first 64 entries).
__device__ __forceinline__ int block_is64(const void* p) {
    __shared__ int s64;
    if (threadIdx.x == 0) {
        const unsigned int* u = (const unsigned int*)p;
        int e = 1;
        #pragma unroll
        for (int i = 0; i < 64; i++)
            if (u[2 * i + 1] != 0u) e = 0;
        s64 = e;
    }
    __syncthreads();
    return s64;
}

__device__ __forceinline__ int ld_idx2(const void* p, long long i, int is64) {
    return is64 ? (int)((const long long*)p)[i] : ((const int*)p)[i];
}

// ======================= degree (detect fused) =======================
__global__ void deg_count(const void* __restrict__ ei, long long E) {
    int is64 = block_is64(ei);
    long long i = (long long)blockIdx.x * blockDim.x + threadIdx.x;
    if (i < E) atomicAdd(&g_deg[ld_idx2(ei, E + i, is64)], 1);
}

// ======================= scan phase 1 (+ dinv fused) =======================
__global__ void scan_partial(int n) {
    int i = blockIdx.x * 256 + threadIdx.x;
    int v = (i < n) ? g_deg[i] : 0;
    if (i < n) g_dinv[i] = rsqrtf((float)(v + 1));  // +1 self loop
    int s = v;
    #pragma unroll
    for (int o = 16; o; o >>= 1) s += __shfl_down_sync(0xffffffffu, s, o);
    __shared__ int ws[8];
    if ((threadIdx.x & 31) == 0) ws[threadIdx.x >> 5] = s;
    __syncthreads();
    if (threadIdx.x == 0) {
        int t = 0;
        #pragma unroll
        for (int k = 0; k < 8; k++) t += ws[k];
        g_bsum[blockIdx.x] = t;
    }
}

// ======================= scan phase 2 (top-scan fused per block) =======================
__global__ void scan_final(int n, long long E) {
    int t = threadIdx.x, lane = t & 31, wid = t >> 5;

    __shared__ int s_off;
    {
        int part = 0;
        for (int i = t; i < blockIdx.x; i += 256) part += g_bsum[i];
        #pragma unroll
        for (int o = 16; o; o >>= 1) part += __shfl_down_sync(0xffffffffu, part, o);
        __shared__ int wr[8];
        if (lane == 0) wr[wid] = part;
        __syncthreads();
        if (t == 0) {
            int s = 0;
            #pragma unroll
            for (int k = 0; k < 8; k++) s += wr[k];
            s_off = s;
        }
        __syncthreads();
    }

    int i = blockIdx.x * 256 + t;
    int v = (i < n) ? g_deg[i] : 0;
    int incl = v;
    #pragma unroll
    for (int o = 1; o < 32; o <<= 1) {
        int u = __shfl_up_sync(0xffffffffu, incl, o);
        if (lane >= o) incl += u;
    }
    __shared__ int ws[8], wso[8];
    if (lane == 31) ws[wid] = incl;
    __syncthreads();
    if (t == 0) {
        int s = 0;
        #pragma unroll
        for (int k = 0; k < 8; k++) { wso[k] = s; s += ws[k]; }
    }
    __syncthreads();
    int excl = incl - v + wso[wid] + s_off;
    if (i < n) { g_rowptr[i] = excl; g_cursor[i] = excl; }
    if (i == n - 1) g_rowptr[n] = (int)E;
}

__global__ void fill_kernel(const void* __restrict__ ei, long long E) {
    int is64 = block_is64(ei);
    long long i = (long long)blockIdx.x * blockDim.x + threadIdx.x;
    if (i >= E) return;
    int s = ld_idx2(ei, i, is64);
    int d = ld_idx2(ei, E + i, is64);
    int pos = atomicAdd(&g_cursor[d], 1);
    g_csrc[pos] = s;
}

// ======================= W transpose into swizzled fp16 images =======================
__global__ void wprep(const float* __restrict__ W1, const float* __restrict__ W2,
                      uint32_t* __restrict__ img) {
    int i = blockIdx.x * 256 + threadIdx.x;      // 2 layers * 128 n * 64 k2
    if (i >= 16384) return;
    int l = i >> 13, rem = i & 8191;
    int nrow = rem >> 6, k2 = rem & 63;
    const float* W = l ? W2 : W1;
    float x0 = W[(2 * k2) * 128 + nrow];
    float x1 = W[(2 * k2 + 1) * 128 + nrow];
    __half2 hv = __floats2half2_rn(x0, x1);      // low = even col
    uint32_t widx = blk_off(nrow, 2 * k2) >> 2;
    img[l * 8192 + widx] = *(uint32_t*)&hv;
}

// ======================= HMMA GEMM: outA = fp16((X @ W) * dinv[row]) =======================
// FP16IN=false: X is fp32 [n,128]; FP16IN=true: X is fp16 [n,128].
#define SM_A 0
#define SM_B 32768
#define GEMM_SMEM 65536

template<bool FP16IN>
__global__ void __launch_bounds__(256, 2)
gemm_tc(const void* __restrict__ Xv, const uint32_t* __restrict__ Wimg,
        __half* __restrict__ outA, int n) {
    extern __shared__ char sm[];
    uint32_t smem_base = smem_u32(sm);
    int t = threadIdx.x;
    int w = t >> 5, lane = t & 31;
    int row0 = blockIdx.x * 128;

    // ---- load X tile into blocked+swizzled SMEM (fp16) ----
    {
        int lrow = t >> 1;
        int kh = t & 1;
        int row = row0 + lrow;
        #pragma unroll 4
        for (int i = 0; i < 16; i++) {
            int k = kh * 64 + i * 4;
            uint32_t u0, u1;
            if (FP16IN) {
                uint2 v = (row < n) ? ((const uint2*)Xv)[(size_t)row * 32 + kh * 16 + i]
                                    : make_uint2(0u, 0u);
                u0 = v.x; u1 = v.y;
            } else {
                float4 v = (row < n) ? ((const float4*)Xv)[(size_t)row * 32 + kh * 16 + i]
                                     : make_float4(0.f, 0.f, 0.f, 0.f);
                __half2 p0 = __floats2half2_rn(v.x, v.y);
                __half2 p1 = __floats2half2_rn(v.z, v.w);
                u0 = *(uint32_t*)&p0; u1 = *(uint32_t*)&p1;
            }
            *(uint32_t*)(sm + SM_A + blk_off(lrow, k))     = u0;
            *(uint32_t*)(sm + SM_A + blk_off(lrow, k + 2)) = u1;
        }
    }
    // ---- copy pre-swizzled W image (32KB) ----
    {
        const uint4* s4 = (const uint4*)Wimg;
        uint4* d4 = (uint4*)(sm + SM_B);
        #pragma unroll
        for (int i = 0; i < 8; i++) d4[t + 256 * i] = s4[t + 256 * i];
    }
    __syncthreads();

    int mwarp = (w & 3) * 32;
    int nwarp = (w >> 2) * 64;

    float acc[2][8][4];
    #pragma unroll
    for (int mi = 0; mi < 2; mi++)
        #pragma unroll
        for (int nj = 0; nj < 8; nj++)
            #pragma unroll
            for (int q = 0; q < 4; q++) acc[mi][nj][q] = 0.f;

    int a_row = mwarp + (lane & 15);
    int a_kof = (lane >> 4) << 3;
    int b_row = nwarp + (lane & 7) + ((lane >> 4) << 3);
    int b_kof = (lane & 8);

    uint32_t Abase = smem_base + SM_A;
    uint32_t Bbase = smem_base + SM_B;

    #pragma unroll
    for (int ks = 0; ks < 8; ks++) {
        int k0 = ks * 16;
        uint32_t a[2][4];
        ldsm4(a[0], Abase + blk_off(a_row,      k0 + a_kof));
        ldsm4(a[1], Abase + blk_off(a_row + 16, k0 + a_kof));
        uint32_t b[4][4];
        #pragma unroll
        for (int g = 0; g < 4; g++)
            ldsm4(b[g], Bbase + blk_off(b_row + g * 16, k0 + b_kof));
        #pragma unroll
        for (int mi = 0; mi < 2; mi++)
            #pragma unroll
            for (int g = 0; g < 4; g++) {
                mma_f16(acc[mi][2 * g],     a[mi], b[g][0], b[g][1]);
                mma_f16(acc[mi][2 * g + 1], a[mi], b[g][2], b[g][3]);
            }
    }

    // ---- epilogue: store msg = h * dinv[row] as fp16 ----
    {
        int g = lane >> 2, i2 = lane & 3;
        #pragma unroll
        for (int mi = 0; mi < 2; mi++) {
            int r0 = row0 + mwarp + mi * 16 + g;
            int r1 = r0 + 8;
            float s0 = (r0 < n) ? g_dinv[r0] : 0.f;
            float s1 = (r1 < n) ? g_dinv[r1] : 0.f;
            #pragma unroll
            for (int nj = 0; nj < 8; nj++) {
                int c = nwarp + nj * 8 + 2 * i2;
                if (r0 < n)
                    *(__half2*)(outA + (size_t)r0 * 128 + c) =
                        __floats2half2_rn(acc[mi][nj][0] * s0, acc[mi][nj][1] * s0);
                if (r1 < n)
                    *(__half2*)(outA + (size_t)r1 * 128 + c) =
                        __floats2half2_rn(acc[mi][nj][2] * s1, acc[mi][nj][3] * s1);
            }
        }
    }
}

// ======================= CSR gather (prescaled fp16 messages, 8-deep batches) =======================
__global__ void gather_kernel(const __half* __restrict__ A, __half* __restrict__ B,
                              const float* __restrict__ bias, int n, int relu) {
    int node = blockIdx.x * (blockDim.x >> 5) + (threadIdx.x >> 5);
    int lane = threadIdx.x & 31;
    if (node >= n) return;
    int beg = g_rowptr[node], end = g_rowptr[node + 1];
    const uint2* A2 = (const uint2*)A;   // 32 uint2 per row

    float4 acc;
    {
        uint2 u = A2[(size_t)node * 32 + lane];   // self msg (already * dinv)
        float2 p0 = __half22float2(*(const __half2*)&u.x);
        float2 p1 = __half22float2(*(const __half2*)&u.y);
        acc.x = p0.x; acc.y = p0.y; acc.z = p1.x; acc.w = p1.y;
    }

    for (int j0 = beg; j0 < end; j0 += 32) {
        int m = min(32, end - j0);
        int idx = (lane < m) ? g_csrc[j0 + lane] : 0;
        int k = 0;
        for (; k + 8 <= m; k += 8) {
            uint2 v[8];
            #pragma unroll
            for (int q = 0; q < 8; q++) {
                int s = __shfl_sync(0xffffffffu, idx, k + q);
                v[q] = A2[(size_t)s * 32 + lane];
            }
            #pragma unroll
            for (int q = 0; q < 8; q++) {
                float2 p0 = __half22float2(*(const __half2*)&v[q].x);
                float2 p1 = __half22float2(*(const __half2*)&v[q].y);
                acc.x += p0.x; acc.y += p0.y; acc.z += p1.x; acc.w += p1.y;
            }
        }
        for (; k < m; k++) {
            int s = __shfl_sync(0xffffffffu, idx, k);
            uint2 u = A2[(size_t)s * 32 + lane];
            float2 p0 = __half22float2(*(const __half2*)&u.x);
            float2 p1 = __half22float2(*(const __half2*)&u.y);
            acc.x += p0.x; acc.y += p0.y; acc.z += p1.x; acc.w += p1.y;
        }
    }

    float sc = g_dinv[node];
    float4 bb = ((const float4*)bias)[lane];
    float4 o;
    o.x = fmaf(acc.x, sc, bb.x);
    o.y = fmaf(acc.y, sc, bb.y);
    o.z = fmaf(acc.z, sc, bb.z);
    o.w = fmaf(acc.w, sc, bb.w);
    if (relu) {
        o.x = fmaxf(o.x, 0.f); o.y = fmaxf(o.y, 0.f);
        o.z = fmaxf(o.z, 0.f); o.w = fmaxf(o.w, 0.f);
    }
    __half2 h0 = __floats2half2_rn(o.x, o.y);
    __half2 h1 = __floats2half2_rn(o.z, o.w);
    uint2 ov = make_uint2(*(uint32_t*)&h0, *(uint32_t*)&h1);
    ((uint2*)B)[(size_t)node * 32 + lane] = ov;
}

// ======================= decode (fp16 z, detect fused) =======================
__global__ void decode_kernel(const void* __restrict__ eli, long long M,
                              const __half* __restrict__ Z, float* __restrict__ out) {
    int is64 = block_is64(eli);
    long long w = (long long)blockIdx.x * (blockDim.x >> 5) + (threadIdx.x >> 5);
    int lane = threadIdx.x & 31;
    if (w >= M) return;
    int s = 0, d = 0;
    if (lane == 0) {
        s = ld_idx2(eli, w, is64);
        d = ld_idx2(eli, M + w, is64);
    }
    s = __shfl_sync(0xffffffffu, s, 0);
    d = __shfl_sync(0xffffffffu, d, 0);
    const uint2* Z2 = (const uint2*)Z;
    uint2 ua = Z2[(size_t)s * 32 + lane];
    uint2 ub = Z2[(size_t)d * 32 + lane];
    float2 a0 = __half22float2(*(const __half2*)&ua.x);
    float2 a1 = __half22float2(*(const __half2*)&ua.y);
    float2 b0 = __half22float2(*(const __half2*)&ub.x);
    float2 b1 = __half22float2(*(const __half2*)&ub.y);
    float sum = a0.x * b0.x + a0.y * b0.y + a1.x * b1.x + a1.y * b1.y;
    #pragma unroll
    for (int o = 16; o; o >>= 1) sum += __shfl_xor_sync(0xffffffffu, sum, o);
    if (lane == 0) out[w] = sum;
}

// ======================= launch =======================
extern "C" void kernel_launch(void* const* d_in, const int* in_sizes, int n_in,
                              void* d_out, int out_size) {
    const float* x   = (const float*)d_in[0];
    const void*  ei  = d_in[1];
    const void*  eli = d_in[2];
    const float* W1  = (const float*)d_in[3];
    const float* b1  = (const float*)d_in[4];
    const float* W2  = (const float*)d_in[5];
    const float* b2  = (const float*)d_in[6];
    float* out = (float*)d_out;

    int n = in_sizes[0] / DIM;
    long long E = in_sizes[1] / 2;
    long long M = in_sizes[2] / 2;

    __half *pA = nullptr, *pB = nullptr;
    uint32_t* pW = nullptr;
    int* pDeg = nullptr;
    cudaGetSymbolAddress((void**)&pA, g_bufA);
    cudaGetSymbolAddress((void**)&pB, g_bufB);
    cudaGetSymbolAddress((void**)&pW, g_Wimg);
    cudaGetSymbolAddress((void**)&pDeg, g_deg);
    cudaFuncSetAttribute(gemm_tc<false>, cudaFuncAttributeMaxDynamicSharedMemorySize, GEMM_SMEM);
    cudaFuncSetAttribute(gemm_tc<true>,  cudaFuncAttributeMaxDynamicSharedMemorySize, GEMM_SMEM);

    // Optional side-stream: fall back to single-stream if creation fails.
    static cudaStream_t sB = nullptr;
    static cudaEvent_t evFork = nullptr, evDinv = nullptr, evJoin = nullptr;
    static int streamTried = 0;
    if (!streamTried) {
        streamTried = 1;
        bool ok = (cudaStreamCreateWithFlags(&sB, cudaStreamNonBlocking) == cudaSuccess);
        ok = ok && (cudaEventCreateWithFlags(&evFork, cudaEventDisableTiming) == cudaSuccess);
        ok = ok && (cudaEventCreateWithFlags(&evDinv, cudaEventDisableTiming) == cudaSuccess);
        ok = ok && (cudaEventCreateWithFlags(&evJoin, cudaEventDisableTiming) == cudaSuccess);
        if (!ok) sB = nullptr;
        cudaGetLastError();
    }
    cudaStream_t sP = sB ? sB : (cudaStream_t)0;

    int nb256 = (n + 255) / 256;
    int eb    = (int)((E + 255) / 256);
    int mbw   = (int)((M + 7) / 8);
    int gbw   = (n + 7) / 8;
    int gemmb = (n + 127) / 128;

    // ---- fork FIRST: preproc is independent of wprep ----
    if (sB) {
        cudaEventRecord(evFork, 0);
        cudaStreamWaitEvent(sB, evFork, 0);
    }

    // preproc on sP: memset, deg_count, scan_partial [-> dinv ready]
    cudaMemsetAsync(pDeg, 0, (size_t)n * sizeof(int), sP);
    deg_count<<<eb, 256, 0, sP>>>(ei, E);
    scan_partial<<<nb256, 256, 0, sP>>>(n);
    if (sB) cudaEventRecord(evDinv, sB);

    // GEMM path on default stream: wprep runs concurrent with preproc head
    wprep<<<64, 256>>>(W1, W2, pW);
    if (sB) cudaStreamWaitEvent(0, evDinv, 0);
    gemm_tc<false><<<gemmb, 256, GEMM_SMEM>>>(x, pW, pA, n);

    // scan_final + fill on sP
    scan_final<<<nb256, 256, 0, sP>>>(n, E);
    fill_kernel<<<eb, 256, 0, sP>>>(ei, E);
    if (sB) cudaEventRecord(evJoin, sB);

    // join
    if (sB) cudaStreamWaitEvent(0, evJoin, 0);

    // serial tail: gather1, gemm2, gather2, decode
    gather_kernel<<<gbw, 256>>>(pA, pB, b1, n, 1);
    gemm_tc<true><<<gemmb, 256, GEMM_SMEM>>>(pB, pW + 8192, pA, n);
    gather_kernel<<<gbw, 256>>>(pA, pB, b2, n, 0);
    decode_kernel<<<mbw, 256>>>(eli, M, pB, out);
}